// round 1
// baseline (speedup 1.0000x reference)
#include <cuda_runtime.h>
#include <math.h>

#define NB    64
#define N0    1083     // 3*19*19
#define N1    4332     // 3*38*38
#define N2    17328    // 3*76*76
#define NTOT  22743
#define MCAND 256
#define NEGV  (-1e9f)
#define NEGH  (-5e8f)
#define NMS_T 0.1f

// scratch (static __device__ — no allocations allowed)
__device__ float g_scores[NB * NTOT];
__device__ int   g_cidx [NB * MCAND];
__device__ float g_cscore[NB * MCAND];

__device__ __forceinline__ float sigmoidf_(float x) { return 1.0f / (1.0f + expf(-x)); }

// map flat per-image index n -> pred pointer + grid cell + stride + anchor (pixels)
__device__ __forceinline__ const float* locate(
    int b, int n,
    const float* __restrict__ l0, const float* __restrict__ l1, const float* __restrict__ l2,
    int& gx, int& gy, float& stride, float& aw, float& ah)
{
    if (n < N0) {
        int a = n / 361, c = n - a * 361; gy = c / 19; gx = c - gy * 19;
        stride = 32.0f;
        aw = (a == 0) ? 116.0f : (a == 1) ? 156.0f : 373.0f;
        ah = (a == 0) ?  90.0f : (a == 1) ? 198.0f : 326.0f;
        return l0 + (size_t)(((b * 3 + a) * 19 + gy) * 19 + gx) * 26;
    } else if (n < N0 + N1) {
        int r = n - N0;
        int a = r / 1444, c = r - a * 1444; gy = c / 38; gx = c - gy * 38;
        stride = 16.0f;
        aw = (a == 0) ? 30.0f : (a == 1) ? 62.0f : 59.0f;
        ah = (a == 0) ? 61.0f : (a == 1) ? 45.0f : 119.0f;
        return l1 + (size_t)(((b * 3 + a) * 38 + gy) * 38 + gx) * 26;
    } else {
        int r = n - N0 - N1;
        int a = r / 5776, c = r - a * 5776; gy = c / 76; gx = c - gy * 76;
        stride = 8.0f;
        aw = (a == 0) ? 10.0f : (a == 1) ? 16.0f : 33.0f;
        ah = (a == 0) ? 13.0f : (a == 1) ? 30.0f : 23.0f;
        return l2 + (size_t)(((b * 3 + a) * 76 + gy) * 76 + gx) * 26;
    }
}

// ---------------- Kernel 1: score every box ----------------
__global__ __launch_bounds__(256) void k_score(
    const float* __restrict__ l0, const float* __restrict__ l1, const float* __restrict__ l2)
{
    int n = blockIdx.x * blockDim.x + threadIdx.x;
    int b = blockIdx.y;
    if (n >= NTOT) return;

    int gx, gy; float stride, aw, ah;
    const float* p = locate(b, n, l0, l1, l2, gx, gy, stride, aw, ah);

    float obj = sigmoidf_(p[4]);
    float loc = sigmoidf_(p[5]);

    float cl[20];
    float m = -INFINITY;
#pragma unroll
    for (int i = 0; i < 20; i++) { cl[i] = p[6 + i]; m = fmaxf(m, cl[i]); }
    float sum = 0.0f;
#pragma unroll
    for (int i = 0; i < 20; i++) sum += expf(cl[i] - m);
    float conf = 1.0f / sum;   // max softmax prob

    bool valid = (obj >= 0.6f) && (obj * conf >= 0.05f) && (loc >= 0.5f);
    // area >= 0 always (SIZE_T = 0, boxes clamped) — omitted
    float score = sqrtf(obj * conf) * sqrtf(loc);   // (obj*conf)^0.5 * loc^0.5
    g_scores[b * NTOT + n] = valid ? score : NEGV;
}

// ---------------- Kernel 2: per-image exact top-256 (radix select on float bits) ----------------
__global__ __launch_bounds__(1024) void k_select()
{
    int b   = blockIdx.x;
    int tid = threadIdx.x;
    int nth = blockDim.x;
    const float* __restrict__ s = g_scores + b * NTOT;

    __shared__ unsigned hist[256];
    __shared__ int sh_chosen, sh_need, sh_takeall;
    __shared__ int cntG, cntE;

    // init candidate slots
    for (int i = tid; i < MCAND; i += nth) {
        g_cidx[b * MCAND + i] = -1;
        g_cscore[b * MCAND + i] = NEGV;
    }
    if (tid == 0) { sh_takeall = 0; sh_need = MCAND; cntG = 0; cntE = 0; }
    __syncthreads();

    unsigned prefix = 0;
    for (int p = 0; p < 4; p++) {
        for (int i = tid; i < 256; i += nth) hist[i] = 0;
        __syncthreads();
        int shift = 24 - 8 * p;
        for (int i = tid; i < NTOT; i += nth) {
            float v = s[i];
            if (v < 0.0f) continue;            // NEGV sentinel; valid scores > 0
            unsigned k = __float_as_uint(v);   // positive float: bits monotonic
            if (p == 0 || (k >> (shift + 8)) == prefix)
                atomicAdd(&hist[(k >> shift) & 255u], 1u);
        }
        __syncthreads();
        if (tid == 0) {
            int need = sh_need;
            unsigned acc = 0; int chosen = -1; unsigned above = 0;
            for (int bb = 255; bb >= 0; bb--) {
                unsigned h = hist[bb];
                if ((int)(acc + h) >= need) { chosen = bb; above = acc; break; }
                acc += h;
            }
            if (chosen < 0) sh_takeall = 1;    // fewer than 256 valid: take all
            else { sh_need = need - (int)above; sh_chosen = chosen; }
        }
        __syncthreads();
        if (sh_takeall) break;
        prefix = (prefix << 8) | (unsigned)sh_chosen;
        __syncthreads();
    }

    int need    = sh_need;
    int takeall = sh_takeall;
    unsigned K  = prefix;          // exact 256th key when !takeall
    int nG      = MCAND - need;    // count strictly greater than K

    for (int i = tid; i < NTOT; i += nth) {
        float v = s[i];
        if (v < 0.0f) continue;
        unsigned k = __float_as_uint(v);
        int pos = -1;
        if (takeall)     pos = atomicAdd(&cntG, 1);
        else if (k > K)  pos = atomicAdd(&cntG, 1);
        else if (k == K) { int e = atomicAdd(&cntE, 1); if (e < need) pos = nG + e; }
        if (pos >= 0 && pos < MCAND) {
            g_cidx[b * MCAND + pos] = i;
            g_cscore[b * MCAND + pos] = v;
        }
    }
}

// ---------------- Kernel 3: decode candidates + Gaussian soft-NMS + top-8 output ----------------
// One warp per image; lane owns candidates c = lane*8 + j in registers.
__global__ __launch_bounds__(32) void k_nms(
    const float* __restrict__ l0, const float* __restrict__ l1, const float* __restrict__ l2,
    float* __restrict__ out)
{
    int b = blockIdx.x;
    int lane = threadIdx.x;

    __shared__ float4 sbox[MCAND];
    __shared__ int    scls[MCAND];

    float x1r[8], y1r[8], x2r[8], y2r[8], a2r[8], sc[8], so[8];
    int cls[8];
    unsigned keptm = 0;

#pragma unroll
    for (int j = 0; j < 8; j++) {
        int c = lane * 8 + j;
        int idx = g_cidx[b * MCAND + c];
        float sv = g_cscore[b * MCAND + c];
        float X1 = 0.f, Y1 = 0.f, X2 = 0.f, Y2 = 0.f;
        int cc = -1;
        if (idx >= 0) {
            int gx, gy; float stride, aw, ah;
            const float* p = locate(b, idx, l0, l1, l2, gx, gy, stride, aw, ah);
            float cx = (sigmoidf_(p[0]) + (float)gx) * stride;
            float cy = (sigmoidf_(p[1]) + (float)gy) * stride;
            float w  = expf(p[2]) * aw;
            float h  = expf(p[3]) * ah;
            X1 = fminf(fmaxf(cx - w * 0.5f, 0.0f), 608.0f);
            Y1 = fminf(fmaxf(cy - h * 0.5f, 0.0f), 608.0f);
            X2 = fminf(fmaxf(cx + w * 0.5f, 0.0f), 608.0f);
            Y2 = fminf(fmaxf(cy + h * 0.5f, 0.0f), 608.0f);
            float best = p[6]; cc = 0;
#pragma unroll
            for (int i = 1; i < 20; i++) {
                float v = p[6 + i];
                if (v > best) { best = v; cc = i; }   // first max, like jnp.argmax
            }
        }
        x1r[j] = X1; y1r[j] = Y1; x2r[j] = X2; y2r[j] = Y2;
        a2r[j] = (X2 - X1 + 1.0f) * (Y2 - Y1 + 1.0f);
        sc[j] = sv; so[j] = sv; cls[j] = cc;
        sbox[c] = make_float4(X1, Y1, X2, Y2);
        scls[c] = cc;
    }
    __syncwarp();

    // soft-NMS: pick global max, decay same-class, repeat. Early exit when max < NMS_T
    // leaves state identical to the reference's remaining no-op iterations.
    for (int it = 0; it < MCAND; it++) {
        float mv = sc[0]; int mi = 0;
#pragma unroll
        for (int j = 1; j < 8; j++) if (sc[j] > mv) { mv = sc[j]; mi = j; }
        int mc = lane * 8 + mi;
#pragma unroll
        for (int off = 16; off; off >>= 1) {
            float ov = __shfl_xor_sync(0xffffffffu, mv, off);
            int   oc = __shfl_xor_sync(0xffffffffu, mc, off);
            if (ov > mv || (ov == mv && oc < mc)) { mv = ov; mc = oc; }
        }
        if (mv < NMS_T) break;

        float4 wb = sbox[mc];
        int wcl = scls[mc];
        float a1 = (wb.z - wb.x + 1.0f) * (wb.w - wb.y + 1.0f);
#pragma unroll
        for (int j = 0; j < 8; j++) {
            if (cls[j] == wcl) {
                float ix1 = fmaxf(wb.x, x1r[j]), iy1 = fmaxf(wb.y, y1r[j]);
                float ix2 = fminf(wb.z, x2r[j]), iy2 = fminf(wb.w, y2r[j]);
                float inter = fmaxf(ix2 - ix1 + 1.0f, 0.0f) * fmaxf(iy2 - iy1 + 1.0f, 0.0f);
                float iou = inter / (a1 + a2r[j] - inter + 1e-16f);
                sc[j] *= expf(-(iou * iou) * 2.0f);   // exp(-iou^2 / 0.5)
            }
        }
        if ((mc >> 3) == lane) {
            sc[mc & 7] = NEGV;
            keptm |= 1u << (mc & 7);
        }
    }

    // top-8 among kept, ranked by ORIGINAL score
    float* ob = out + (size_t)b * 48;
    for (int k = 0; k < 8; k++) {
        float mv = NEGV; int mi = 0;
#pragma unroll
        for (int j = 0; j < 8; j++) {
            float v = ((keptm >> j) & 1u) ? so[j] : NEGV;
            if (v > mv) { mv = v; mi = j; }
        }
        int mc = lane * 8 + mi;
#pragma unroll
        for (int off = 16; off; off >>= 1) {
            float ov = __shfl_xor_sync(0xffffffffu, mv, off);
            int   oc = __shfl_xor_sync(0xffffffffu, mc, off);
            if (ov > mv || (ov == mv && oc < mc)) { mv = ov; mc = oc; }
        }
        if (mv > NEGH) {
            if ((mc >> 3) == lane) {
                int j = mc & 7;
                ob[k * 6 + 0] = x1r[j];
                ob[k * 6 + 1] = y1r[j];
                ob[k * 6 + 2] = x2r[j];
                ob[k * 6 + 3] = y2r[j];
                ob[k * 6 + 4] = so[j];
                ob[k * 6 + 5] = (float)cls[j];
                keptm &= ~(1u << j);
            }
        } else if (lane == 0) {
#pragma unroll
            for (int i = 0; i < 6; i++) ob[k * 6 + i] = 0.0f;
        }
    }
}

extern "C" void kernel_launch(void* const* d_in, const int* in_sizes, int n_in,
                              void* d_out, int out_size)
{
    const float* l0 = (const float*)d_in[0];
    const float* l1 = (const float*)d_in[1];
    const float* l2 = (const float*)d_in[2];
    float* out = (float*)d_out;

    dim3 g1((NTOT + 255) / 256, NB);
    k_score<<<g1, 256>>>(l0, l1, l2);
    k_select<<<NB, 1024>>>();
    k_nms<<<NB, 32>>>(l0, l1, l2, out);
}

// round 2
// speedup vs baseline: 4.2042x; 4.2042x over previous
#include <cuda_runtime.h>
#include <math.h>

#define NB    64
#define N0    1083     // 3*19*19
#define N1    4332     // 3*38*38
#define N2    17328    // 3*76*76
#define NTOT  22743
#define MCAND 256
#define NEGV  (-1e9f)
#define NMS_T 0.1f

// scratch (static __device__ — no allocations allowed)
__device__ float    g_scores[NB * NTOT];
__device__ int      g_cidx  [NB * MCAND];
__device__ float    g_cscore[NB * MCAND];
__device__ float4   g_cbox  [NB * MCAND];
__device__ float    g_carea [NB * MCAND];
__device__ int      g_ccls  [NB * MCAND];
__device__ unsigned g_kept  [NB * 8];

__device__ __forceinline__ unsigned redux_umax(unsigned v) {
    unsigned r; asm("redux.sync.max.u32 %0, %1, 0xffffffff;" : "=r"(r) : "r"(v)); return r;
}
__device__ __forceinline__ unsigned redux_umin(unsigned v) {
    unsigned r; asm("redux.sync.min.u32 %0, %1, 0xffffffff;" : "=r"(r) : "r"(v)); return r;
}

// map flat per-image index n -> pred pointer + grid cell + stride + anchor (pixels)
__device__ __forceinline__ const float* locate(
    int b, int n,
    const float* __restrict__ l0, const float* __restrict__ l1, const float* __restrict__ l2,
    int& gx, int& gy, float& stride, float& aw, float& ah)
{
    if (n < N0) {
        int a = n / 361, c = n - a * 361; gy = c / 19; gx = c - gy * 19;
        stride = 32.0f;
        aw = (a == 0) ? 116.0f : (a == 1) ? 156.0f : 373.0f;
        ah = (a == 0) ?  90.0f : (a == 1) ? 198.0f : 326.0f;
        return l0 + (size_t)(((b * 3 + a) * 19 + gy) * 19 + gx) * 26;
    } else if (n < N0 + N1) {
        int r = n - N0;
        int a = r / 1444, c = r - a * 1444; gy = c / 38; gx = c - gy * 38;
        stride = 16.0f;
        aw = (a == 0) ? 30.0f : (a == 1) ? 62.0f : 59.0f;
        ah = (a == 0) ? 61.0f : (a == 1) ? 45.0f : 119.0f;
        return l1 + (size_t)(((b * 3 + a) * 38 + gy) * 38 + gx) * 26;
    } else {
        int r = n - N0 - N1;
        int a = r / 5776, c = r - a * 5776; gy = c / 76; gx = c - gy * 76;
        stride = 8.0f;
        aw = (a == 0) ? 10.0f : (a == 1) ? 16.0f : 33.0f;
        ah = (a == 0) ? 13.0f : (a == 1) ? 30.0f : 23.0f;
        return l2 + (size_t)(((b * 3 + a) * 76 + gy) * 76 + gx) * 26;
    }
}

// ---------------- Kernel 1: score every box (smem-staged, coalesced) ----------------
template<int NL, int OFF>
__global__ __launch_bounds__(128) void k_score_lvl(const float* __restrict__ in)
{
    __shared__ float sm[128 * 27];     // padded stride 27 -> conflict-free LDS
    int base  = blockIdx.x * 128;
    int total = NB * NL;
    int nrec  = total - base; if (nrec > 128) nrec = 128;
    int nfl   = nrec * 26;
    const float* __restrict__ src = in + (size_t)base * 26;

    for (int f = threadIdx.x; f < nfl; f += 128) {
        unsigned rec = (unsigned)f / 26u;
        unsigned col = (unsigned)f - rec * 26u;
        sm[rec * 27 + col] = src[f];
    }
    __syncthreads();

    int t = threadIdx.x;
    if (t < nrec) {
        const float* p = sm + t * 27;
        float obj = 1.0f / (1.0f + expf(-p[4]));
        float loc = 1.0f / (1.0f + expf(-p[5]));
        float m = p[6];
#pragma unroll
        for (int i = 1; i < 20; i++) m = fmaxf(m, p[6 + i]);
        float s = 0.0f;
#pragma unroll
        for (int i = 0; i < 20; i++) s += expf(p[6 + i] - m);
        float conf = 1.0f / s;     // max softmax prob

        bool valid = (obj >= 0.6f) && (obj * conf >= 0.05f) && (loc >= 0.5f);
        float score = sqrtf(obj * conf) * sqrtf(loc);   // (obj*conf)^0.5 * loc^0.5

        int r = base + t;
        int b = r / NL;
        int n = r - b * NL;
        g_scores[b * NTOT + OFF + n] = valid ? score : NEGV;
    }
}

// ---------------- Kernel 2: per-image exact top-256 (radix select on float bits) ----------------
__global__ __launch_bounds__(1024) void k_select()
{
    int b   = blockIdx.x;
    int tid = threadIdx.x;
    int nth = blockDim.x;
    const float* __restrict__ s = g_scores + b * NTOT;

    __shared__ unsigned hist[256];
    __shared__ int sh_chosen, sh_need, sh_takeall;
    __shared__ int cntG, cntE;

    for (int i = tid; i < MCAND; i += nth) {
        g_cidx[b * MCAND + i] = -1;
        g_cscore[b * MCAND + i] = NEGV;
    }
    if (tid < 8) g_kept[b * 8 + tid] = 0u;
    if (tid == 0) { sh_takeall = 0; sh_need = MCAND; cntG = 0; cntE = 0; }
    __syncthreads();

    unsigned prefix = 0;
    for (int p = 0; p < 4; p++) {
        for (int i = tid; i < 256; i += nth) hist[i] = 0;
        __syncthreads();
        int shift = 24 - 8 * p;
        for (int i = tid; i < NTOT; i += nth) {
            float v = s[i];
            if (v < 0.0f) continue;            // NEGV sentinel; valid scores > 0
            unsigned k = __float_as_uint(v);   // positive float: bits monotonic
            if (p == 0 || (k >> (shift + 8)) == prefix)
                atomicAdd(&hist[(k >> shift) & 255u], 1u);
        }
        __syncthreads();
        if (tid == 0) {
            int need = sh_need;
            unsigned acc = 0; int chosen = -1; unsigned above = 0;
            for (int bb = 255; bb >= 0; bb--) {
                unsigned h = hist[bb];
                if ((int)(acc + h) >= need) { chosen = bb; above = acc; break; }
                acc += h;
            }
            if (chosen < 0) sh_takeall = 1;    // fewer than 256 valid: take all
            else { sh_need = need - (int)above; sh_chosen = chosen; }
        }
        __syncthreads();
        if (sh_takeall) break;
        prefix = (prefix << 8) | (unsigned)sh_chosen;
        __syncthreads();
    }

    int need    = sh_need;
    int takeall = sh_takeall;
    unsigned K  = prefix;          // exact 256th key when !takeall
    int nG      = MCAND - need;    // count strictly greater than K

    for (int i = tid; i < NTOT; i += nth) {
        float v = s[i];
        if (v < 0.0f) continue;
        unsigned k = __float_as_uint(v);
        int pos = -1;
        if (takeall)     pos = atomicAdd(&cntG, 1);
        else if (k > K)  pos = atomicAdd(&cntG, 1);
        else if (k == K) { int e = atomicAdd(&cntE, 1); if (e < need) pos = nG + e; }
        if (pos >= 0 && pos < MCAND) {
            g_cidx[b * MCAND + pos] = i;
            g_cscore[b * MCAND + pos] = v;
        }
    }
}

// ---------------- Kernel 3: decode candidate boxes + class ----------------
__global__ __launch_bounds__(256) void k_decode(
    const float* __restrict__ l0, const float* __restrict__ l1, const float* __restrict__ l2)
{
    int b = blockIdx.x;
    int c = threadIdx.x;
    int slot = b * MCAND + c;
    int idx = g_cidx[slot];

    float4 bx = make_float4(0.f, 0.f, 0.f, 0.f);
    int cc = -1;
    if (idx >= 0) {
        int gx, gy; float stride, aw, ah;
        const float* p = locate(b, idx, l0, l1, l2, gx, gy, stride, aw, ah);
        float cx = (1.0f / (1.0f + expf(-p[0])) + (float)gx) * stride;
        float cy = (1.0f / (1.0f + expf(-p[1])) + (float)gy) * stride;
        float w  = expf(p[2]) * aw;
        float h  = expf(p[3]) * ah;
        bx.x = fminf(fmaxf(cx - w * 0.5f, 0.0f), 608.0f);
        bx.y = fminf(fmaxf(cy - h * 0.5f, 0.0f), 608.0f);
        bx.z = fminf(fmaxf(cx + w * 0.5f, 0.0f), 608.0f);
        bx.w = fminf(fmaxf(cy + h * 0.5f, 0.0f), 608.0f);
        float best = p[6]; cc = 0;
#pragma unroll
        for (int i = 1; i < 20; i++) {
            float v = p[6 + i];
            if (v > best) { best = v; cc = i; }   // first max, like jnp.argmax
        }
    }
    g_cbox[slot]  = bx;
    g_carea[slot] = (bx.z - bx.x + 1.0f) * (bx.w - bx.y + 1.0f);
    g_ccls[slot]  = cc;
}

// ---------------- Kernel 4: per-(image,class) Gaussian soft-NMS ----------------
// Soft-NMS decays only same-class scores, and M=256 steps always suffice to
// drain every candidate => the kept set decomposes exactly per class.
// One warp per (image, class); lane owns slots j*32+lane.
__global__ __launch_bounds__(32) void k_nms()
{
    int b = blockIdx.x, cl = blockIdx.y, lane = threadIdx.x;
    __shared__ float4 sb[MCAND];
    __shared__ float  sa[MCAND];

    unsigned key[8]; float sc[8]; float4 bx[8]; float a2[8]; bool act[8];
    unsigned any = 0;
#pragma unroll
    for (int j = 0; j < 8; j++) {
        int slot = j * 32 + lane;
        int g = b * MCAND + slot;
        int cc  = g_ccls[g];
        float s = g_cscore[g];
        act[j] = (cc == cl);
        key[j] = act[j] ? __float_as_uint(s) : 0u;
        sc[j]  = s;
        float4 B = g_cbox[g];
        bx[j] = B;
        a2[j] = g_carea[g];
        sb[slot] = B;
        sa[slot] = a2[j];
        any |= key[j];
    }
    __syncwarp();
    if (redux_umax(any) == 0u) return;      // class absent in this image

    unsigned keptloc = 0;
    for (int it = 0; it < MCAND; it++) {
        unsigned lm = 0, li = 0;
#pragma unroll
        for (int j = 0; j < 8; j++)
            if (key[j] > lm) { lm = key[j]; li = (unsigned)(j * 32 + lane); }
        unsigned wm = redux_umax(lm);
        if (__uint_as_float(wm) < NMS_T) break;   // includes wm==0
        unsigned cand = (lm == wm) ? li : 0xFFFFFFFFu;
        unsigned wi = redux_umin(cand);           // first-index tie-break (exact)

        float4 wb = sb[wi];
        float  a1 = sa[wi];
#pragma unroll
        for (int j = 0; j < 8; j++) {
            if (act[j]) {
                float ix1 = fmaxf(wb.x, bx[j].x), iy1 = fmaxf(wb.y, bx[j].y);
                float ix2 = fminf(wb.z, bx[j].z), iy2 = fminf(wb.w, bx[j].w);
                float inter = fmaxf(ix2 - ix1 + 1.0f, 0.0f) * fmaxf(iy2 - iy1 + 1.0f, 0.0f);
                float iou = inter / (a1 + a2[j] - inter + 1e-16f);
                sc[j] *= expf(-(iou * iou) * 2.0f);   // exp(-iou^2 / 0.5)
                key[j] = __float_as_uint(sc[j]);
            }
            if ((unsigned)(j * 32 + lane) == wi) {    // remove winner, mark kept
                act[j] = false;
                key[j] = 0u;
                keptloc |= 1u << j;
            }
        }
    }
#pragma unroll
    for (int j = 0; j < 8; j++)
        if (keptloc & (1u << j)) atomicOr(&g_kept[b * 8 + j], 1u << lane);
}

// ---------------- Kernel 5: top-8 among kept by ORIGINAL score ----------------
__global__ __launch_bounds__(32) void k_final(float* __restrict__ out)
{
    int b = blockIdx.x, lane = threadIdx.x;
    unsigned key[8]; float so[8];
#pragma unroll
    for (int j = 0; j < 8; j++) {
        int slot = j * 32 + lane;
        int g = b * MCAND + slot;
        bool k = (g_kept[b * 8 + j] >> lane) & 1u;
        float s = g_cscore[g];
        so[j]  = s;
        key[j] = k ? __float_as_uint(s) : 0u;   // kept scores are > 0
    }
    float* ob = out + (size_t)b * 48;
    for (int k = 0; k < 8; k++) {
        unsigned lm = 0, li = 0;
#pragma unroll
        for (int j = 0; j < 8; j++)
            if (key[j] > lm) { lm = key[j]; li = (unsigned)(j * 32 + lane); }
        unsigned wm = redux_umax(lm);
        if (wm == 0u) {
            if (lane == 0) {
#pragma unroll
                for (int i = 0; i < 6; i++) ob[k * 6 + i] = 0.0f;
            }
            continue;
        }
        unsigned cand = (lm == wm) ? li : 0xFFFFFFFFu;
        unsigned wi = redux_umin(cand);
#pragma unroll
        for (int j = 0; j < 8; j++) {
            if ((unsigned)(j * 32 + lane) == wi) {
                int g = b * MCAND + j * 32 + lane;
                float4 B = g_cbox[g];
                ob[k * 6 + 0] = B.x;
                ob[k * 6 + 1] = B.y;
                ob[k * 6 + 2] = B.z;
                ob[k * 6 + 3] = B.w;
                ob[k * 6 + 4] = so[j];
                ob[k * 6 + 5] = (float)g_ccls[g];
                key[j] = 0u;
            }
        }
    }
}

extern "C" void kernel_launch(void* const* d_in, const int* in_sizes, int n_in,
                              void* d_out, int out_size)
{
    const float* l0 = (const float*)d_in[0];
    const float* l1 = (const float*)d_in[1];
    const float* l2 = (const float*)d_in[2];
    float* out = (float*)d_out;

    k_score_lvl<N0, 0>      <<<(NB * N0 + 127) / 128, 128>>>(l0);
    k_score_lvl<N1, N0>     <<<(NB * N1 + 127) / 128, 128>>>(l1);
    k_score_lvl<N2, N0 + N1><<<(NB * N2 + 127) / 128, 128>>>(l2);
    k_select<<<NB, 1024>>>();
    k_decode<<<NB, 256>>>(l0, l1, l2);
    k_nms<<<dim3(NB, 20), 32>>>();
    k_final<<<NB, 32>>>(out);
}

// round 3
// speedup vs baseline: 4.5583x; 1.0842x over previous
#include <cuda_runtime.h>
#include <math.h>

#define NB    64
#define N0    1083     // 3*19*19
#define N1    4332     // 3*38*38
#define N2    17328    // 3*76*76
#define NTOT  22743
#define MCAND 256
#define NEGV  (-1e9f)
#define NMS_T 0.1f

// scratch (static __device__ — no allocations allowed)
__device__ int      g_ncand[NB];
__device__ float    g_vsc  [NB * NTOT];   // compacted valid scores per image
__device__ int      g_vidx [NB * NTOT];   // compacted flat indices per image
__device__ float    g_cscore[NB * MCAND];
__device__ float4   g_cbox  [NB * MCAND];
__device__ float    g_carea [NB * MCAND];
__device__ int      g_ccls  [NB * MCAND];
__device__ unsigned g_kept  [NB * 8];

__device__ __forceinline__ unsigned redux_umax(unsigned v) {
    unsigned r; asm("redux.sync.max.u32 %0, %1, 0xffffffff;" : "=r"(r) : "r"(v)); return r;
}
__device__ __forceinline__ unsigned redux_umin(unsigned v) {
    unsigned r; asm("redux.sync.min.u32 %0, %1, 0xffffffff;" : "=r"(r) : "r"(v)); return r;
}

// map flat per-image index n -> pred pointer + grid cell + anchor (pixels)
__device__ __forceinline__ const float* locate(
    int b, int n,
    const float* __restrict__ l0, const float* __restrict__ l1, const float* __restrict__ l2,
    int& gx, int& gy, float& stride, float& aw, float& ah)
{
    if (n < N0) {
        int a = n / 361, c = n - a * 361; gy = c / 19; gx = c - gy * 19;
        stride = 32.0f;
        aw = (a == 0) ? 116.0f : (a == 1) ? 156.0f : 373.0f;
        ah = (a == 0) ?  90.0f : (a == 1) ? 198.0f : 326.0f;
        return l0 + (size_t)(((b * 3 + a) * 19 + gy) * 19 + gx) * 26;
    } else if (n < N0 + N1) {
        int r = n - N0;
        int a = r / 1444, c = r - a * 1444; gy = c / 38; gx = c - gy * 38;
        stride = 16.0f;
        aw = (a == 0) ? 30.0f : (a == 1) ? 62.0f : 59.0f;
        ah = (a == 0) ? 61.0f : (a == 1) ? 45.0f : 119.0f;
        return l1 + (size_t)(((b * 3 + a) * 38 + gy) * 38 + gx) * 26;
    } else {
        int r = n - N0 - N1;
        int a = r / 5776, c = r - a * 5776; gy = c / 76; gx = c - gy * 76;
        stride = 8.0f;
        aw = (a == 0) ? 10.0f : (a == 1) ? 16.0f : 33.0f;
        ah = (a == 0) ? 13.0f : (a == 1) ? 30.0f : 23.0f;
        return l2 + (size_t)(((b * 3 + a) * 76 + gy) * 76 + gx) * 26;
    }
}

// ---------------- Kernel 0: init counters ----------------
__global__ void k_init() {
    if (threadIdx.x < NB) g_ncand[threadIdx.x] = 0;
}

// ---------------- Kernel 1: score + compact valid candidates ----------------
template<int NL, int OFF>
__global__ __launch_bounds__(256) void k_score_lvl(const float* __restrict__ in)
{
    __shared__ float sm[256 * 27];     // padded stride 27 -> conflict-free LDS
    int base  = blockIdx.x * 256;
    int total = NB * NL;
    int nrec  = total - base; if (nrec > 256) nrec = 256;
    int nfl   = nrec * 26;
    const float* __restrict__ src = in + (size_t)base * 26;

    // float4 staged coalesced load (src is 16B-aligned: base*104 % 16 == 0)
    int nf4 = nfl >> 2;
    for (int q = threadIdx.x; q < nf4; q += 256) {
        float4 v = reinterpret_cast<const float4*>(src)[q];
        int f = q * 4;
#pragma unroll
        for (int e = 0; e < 4; e++) {
            int ff = f + e;
            int rec = ff / 26, col = ff - rec * 26;
            sm[rec * 27 + col] = (&v.x)[e];
        }
    }
    for (int f = (nf4 << 2) + threadIdx.x; f < nfl; f += 256) {
        int rec = f / 26, col = f - rec * 26;
        sm[rec * 27 + col] = src[f];
    }
    __syncthreads();

    int t = threadIdx.x;
    bool valid = false;
    float score = 0.0f;
    int bimg = 0, nloc = 0;
    if (t < nrec) {
        const float* p = sm + t * 27;
        float obj = 1.0f / (1.0f + expf(-p[4]));
        float loc = 1.0f / (1.0f + expf(-p[5]));
        float m = p[6];
#pragma unroll
        for (int i = 1; i < 20; i++) m = fmaxf(m, p[6 + i]);
        float s = 0.0f;
#pragma unroll
        for (int i = 0; i < 20; i++) s += expf(p[6 + i] - m);
        float conf = 1.0f / s;
        valid = (obj >= 0.6f) && (obj * conf >= 0.05f) && (loc >= 0.5f);
        score = sqrtf(obj * conf) * sqrtf(loc);
        int r = base + t;
        bimg = r / NL;
        nloc = r - bimg * NL;
    }

    // warp-aggregated append (a warp spans at most 2 images)
    unsigned lane = threadIdx.x & 31u;
    int b0 = __shfl_sync(0xffffffffu, bimg, 0);
    bool same = (bimg == b0);
    unsigned m_same = __ballot_sync(0xffffffffu, valid && same);
    unsigned m_diff = __ballot_sync(0xffffffffu, valid && !same);
    int pos = -1, bw = 0;
    if (m_same) {
        int leader = __ffs(m_same) - 1;
        int bs = 0;
        if ((int)lane == leader) bs = atomicAdd(&g_ncand[b0], __popc(m_same));
        bs = __shfl_sync(0xffffffffu, bs, leader);
        if (valid && same) { pos = bs + __popc(m_same & ((1u << lane) - 1u)); bw = b0; }
    }
    if (m_diff) {
        int leader = __ffs(m_diff) - 1;
        int b1 = __shfl_sync(0xffffffffu, bimg, leader);
        int bs = 0;
        if ((int)lane == leader) bs = atomicAdd(&g_ncand[b1], __popc(m_diff));
        bs = __shfl_sync(0xffffffffu, bs, leader);
        if (valid && !same) { pos = bs + __popc(m_diff & ((1u << lane) - 1u)); bw = b1; }
    }
    if (pos >= 0) {
        g_vsc [(size_t)bw * NTOT + pos] = score;
        g_vidx[(size_t)bw * NTOT + pos] = OFF + nloc;
    }
}

// ---------------- Kernel 2: exact top-256 (radix, parallel scan) + fused decode ----------------
__global__ __launch_bounds__(512) void k_select(
    const float* __restrict__ l0, const float* __restrict__ l1, const float* __restrict__ l2)
{
    int b = blockIdx.x, tid = threadIdx.x;
    const int nth = 512;
    int n = g_ncand[b];
    const float* __restrict__ vs = g_vsc  + (size_t)b * NTOT;
    const int*   __restrict__ vi = g_vidx + (size_t)b * NTOT;

    __shared__ unsigned hist[256];
    __shared__ unsigned suf[256];
    __shared__ int sh_chosen, sh_need, sh_abv, cntG, cntE;
    __shared__ int   s_idx[MCAND];
    __shared__ float s_sc [MCAND];

    for (int i = tid; i < MCAND; i += nth) { s_idx[i] = -1; s_sc[i] = NEGV; }
    if (tid < 8) g_kept[b * 8 + tid] = 0u;
    if (tid == 0) { sh_need = MCAND; cntG = 0; cntE = 0; }
    __syncthreads();

    if (n <= MCAND) {
        for (int i = tid; i < n; i += nth) { s_idx[i] = vi[i]; s_sc[i] = vs[i]; }
    } else {
        unsigned prefix = 0;
        for (int p = 0; p < 4; p++) {
            if (tid < 256) hist[tid] = 0;
            __syncthreads();
            int shift = 24 - 8 * p;
            for (int i = tid; i < n; i += nth) {
                unsigned k = __float_as_uint(vs[i]);   // all compacted scores > 0
                if (p == 0 || (k >> (shift + 8)) == prefix)
                    atomicAdd(&hist[(k >> shift) & 255u], 1u);
            }
            __syncthreads();
            int need = sh_need;
            if (tid < 256) suf[tid] = hist[tid];
            __syncthreads();
#pragma unroll
            for (int off = 1; off < 256; off <<= 1) {       // suffix sum
                unsigned v = 0;
                if (tid < 256 && tid + off < 256) v = suf[tid + off];
                __syncthreads();
                if (tid < 256) suf[tid] += v;
                __syncthreads();
            }
            if (tid < 256) {
                unsigned here = suf[tid];
                unsigned abv  = (tid == 255) ? 0u : suf[tid + 1];
                if ((int)here >= need && (int)abv < need) { sh_chosen = tid; sh_abv = (int)abv; }
            }
            __syncthreads();
            if (tid == 0) sh_need = need - sh_abv;
            __syncthreads();
            prefix = (prefix << 8) | (unsigned)sh_chosen;
        }
        int need = sh_need;
        unsigned K = prefix;               // exact 256th key
        int nG = MCAND - need;
        for (int i = tid; i < n; i += nth) {
            float v = vs[i];
            unsigned k = __float_as_uint(v);
            int pos = -1;
            if (k > K)       pos = atomicAdd(&cntG, 1);
            else if (k == K) { int e = atomicAdd(&cntE, 1); if (e < need) pos = nG + e; }
            if (pos >= 0) { s_idx[pos] = vi[i]; s_sc[pos] = v; }
        }
    }
    __syncthreads();

    // export scores + fused decode (threads 0..255)
    for (int c = tid; c < MCAND; c += nth) g_cscore[b * MCAND + c] = s_sc[c];
    if (tid < MCAND) {
        int slot = b * MCAND + tid;
        int idx = s_idx[tid];
        float4 bx = make_float4(0.f, 0.f, 0.f, 0.f);
        int cc = -1;
        if (idx >= 0) {
            int gx, gy; float stride, aw, ah;
            const float* p = locate(b, idx, l0, l1, l2, gx, gy, stride, aw, ah);
            float cx = (1.0f / (1.0f + expf(-p[0])) + (float)gx) * stride;
            float cy = (1.0f / (1.0f + expf(-p[1])) + (float)gy) * stride;
            float w  = expf(p[2]) * aw;
            float h  = expf(p[3]) * ah;
            bx.x = fminf(fmaxf(cx - w * 0.5f, 0.0f), 608.0f);
            bx.y = fminf(fmaxf(cy - h * 0.5f, 0.0f), 608.0f);
            bx.z = fminf(fmaxf(cx + w * 0.5f, 0.0f), 608.0f);
            bx.w = fminf(fmaxf(cy + h * 0.5f, 0.0f), 608.0f);
            float best = p[6]; cc = 0;
#pragma unroll
            for (int i = 1; i < 20; i++) {
                float v = p[6 + i];
                if (v > best) { best = v; cc = i; }   // first max, like jnp.argmax
            }
        }
        g_cbox[slot]  = bx;
        g_carea[slot] = (bx.z - bx.x + 1.0f) * (bx.w - bx.y + 1.0f);
        g_ccls[slot]  = cc;
    }
}

// ---------------- Kernel 3: per-(image,class) Gaussian soft-NMS ----------------
// Soft-NMS only decays same-class scores and 256 steps drain every candidate,
// so the kept set decomposes exactly per class. One warp per (image, class).
__global__ __launch_bounds__(32) void k_nms()
{
    int b = blockIdx.x, cl = blockIdx.y, lane = threadIdx.x;
    __shared__ float4 sb[MCAND];
    __shared__ float  sa[MCAND];

    unsigned key[8]; float sc[8]; float4 bx[8]; float a2[8]; bool act[8];
    unsigned any = 0;
#pragma unroll
    for (int j = 0; j < 8; j++) {
        int slot = j * 32 + lane;
        int g = b * MCAND + slot;
        int cc  = g_ccls[g];
        float s = g_cscore[g];
        act[j] = (cc == cl);
        key[j] = act[j] ? __float_as_uint(s) : 0u;
        sc[j]  = s;
        float4 B = g_cbox[g];
        bx[j] = B;
        a2[j] = g_carea[g];
        sb[slot] = B;
        sa[slot] = a2[j];
        any |= key[j];
    }
    __syncwarp();
    if (redux_umax(any) == 0u) return;      // class absent in this image

    unsigned keptloc = 0;
    for (int it = 0; it < MCAND; it++) {
        unsigned lm = 0, li = 0;
#pragma unroll
        for (int j = 0; j < 8; j++)
            if (key[j] > lm) { lm = key[j]; li = (unsigned)(j * 32 + lane); }
        unsigned wm = redux_umax(lm);
        if (__uint_as_float(wm) < NMS_T) break;   // includes wm==0
        unsigned cand = (lm == wm) ? li : 0xFFFFFFFFu;
        unsigned wi = redux_umin(cand);           // first-index tie-break (exact)

        float4 wb = sb[wi];
        float  a1 = sa[wi];
#pragma unroll
        for (int j = 0; j < 8; j++) {
            if (act[j]) {
                float ix1 = fmaxf(wb.x, bx[j].x), iy1 = fmaxf(wb.y, bx[j].y);
                float ix2 = fminf(wb.z, bx[j].z), iy2 = fminf(wb.w, bx[j].w);
                float inter = fmaxf(ix2 - ix1 + 1.0f, 0.0f) * fmaxf(iy2 - iy1 + 1.0f, 0.0f);
                float iou = inter / (a1 + a2[j] - inter + 1e-16f);
                sc[j] *= expf(-(iou * iou) * 2.0f);   // exp(-iou^2 / 0.5)
                key[j] = __float_as_uint(sc[j]);
            }
            if ((unsigned)(j * 32 + lane) == wi) {
                act[j] = false;
                key[j] = 0u;
                keptloc |= 1u << j;
            }
        }
    }
#pragma unroll
    for (int j = 0; j < 8; j++)
        if (keptloc & (1u << j)) atomicOr(&g_kept[b * 8 + j], 1u << lane);
}

// ---------------- Kernel 4: top-8 among kept by ORIGINAL score ----------------
__global__ __launch_bounds__(32) void k_final(float* __restrict__ out)
{
    int b = blockIdx.x, lane = threadIdx.x;
    unsigned key[8]; float so[8];
#pragma unroll
    for (int j = 0; j < 8; j++) {
        int g = b * MCAND + j * 32 + lane;
        bool k = (g_kept[b * 8 + j] >> lane) & 1u;
        float s = g_cscore[g];
        so[j]  = s;
        key[j] = k ? __float_as_uint(s) : 0u;   // kept scores are > 0
    }
    float* ob = out + (size_t)b * 48;
    for (int k = 0; k < 8; k++) {
        unsigned lm = 0, li = 0;
#pragma unroll
        for (int j = 0; j < 8; j++)
            if (key[j] > lm) { lm = key[j]; li = (unsigned)(j * 32 + lane); }
        unsigned wm = redux_umax(lm);
        if (wm == 0u) {
            if (lane == 0) {
#pragma unroll
                for (int i = 0; i < 6; i++) ob[k * 6 + i] = 0.0f;
            }
            continue;
        }
        unsigned cand = (lm == wm) ? li : 0xFFFFFFFFu;
        unsigned wi = redux_umin(cand);
#pragma unroll
        for (int j = 0; j < 8; j++) {
            if ((unsigned)(j * 32 + lane) == wi) {
                int g = b * MCAND + j * 32 + lane;
                float4 B = g_cbox[g];
                ob[k * 6 + 0] = B.x;
                ob[k * 6 + 1] = B.y;
                ob[k * 6 + 2] = B.z;
                ob[k * 6 + 3] = B.w;
                ob[k * 6 + 4] = so[j];
                ob[k * 6 + 5] = (float)g_ccls[g];
                key[j] = 0u;
            }
        }
    }
}

extern "C" void kernel_launch(void* const* d_in, const int* in_sizes, int n_in,
                              void* d_out, int out_size)
{
    const float* l0 = (const float*)d_in[0];
    const float* l1 = (const float*)d_in[1];
    const float* l2 = (const float*)d_in[2];
    float* out = (float*)d_out;

    k_init<<<1, 64>>>();
    k_score_lvl<N0, 0>      <<<(NB * N0 + 255) / 256, 256>>>(l0);
    k_score_lvl<N1, N0>     <<<(NB * N1 + 255) / 256, 256>>>(l1);
    k_score_lvl<N2, N0 + N1><<<(NB * N2 + 255) / 256, 256>>>(l2);
    k_select<<<NB, 512>>>(l0, l1, l2);
    k_nms<<<dim3(NB, 20), 32>>>();
    k_final<<<NB, 32>>>(out);
}

// round 4
// speedup vs baseline: 4.5982x; 1.0088x over previous
#include <cuda_runtime.h>
#include <math.h>

#define NB    64
#define N0    1083     // 3*19*19
#define N1    4332     // 3*38*38
#define N2    17328    // 3*76*76
#define NTOT  22743
#define MCAND 256
#define NEGV  (-1e9f)
#define NMS_T 0.1f

// scratch (static __device__ — no allocations allowed)
__device__ int      g_ncand[NB];
__device__ float    g_vsc  [NB * NTOT];   // compacted valid scores per image
__device__ int      g_vidx [NB * NTOT];   // compacted flat indices per image
__device__ float    g_cscore[NB * MCAND];
__device__ float4   g_cbox  [NB * MCAND];
__device__ float    g_carea [NB * MCAND];
__device__ int      g_ccls  [NB * MCAND];
__device__ unsigned g_kept  [NB * 8];

__device__ __forceinline__ unsigned redux_umax(unsigned v) {
    unsigned r; asm("redux.sync.max.u32 %0, %1, 0xffffffff;" : "=r"(r) : "r"(v)); return r;
}
__device__ __forceinline__ unsigned redux_umin(unsigned v) {
    unsigned r; asm("redux.sync.min.u32 %0, %1, 0xffffffff;" : "=r"(r) : "r"(v)); return r;
}

// map flat per-image index n -> pred pointer + grid cell + anchor (pixels)
__device__ __forceinline__ const float* locate(
    int b, int n,
    const float* __restrict__ l0, const float* __restrict__ l1, const float* __restrict__ l2,
    int& gx, int& gy, float& stride, float& aw, float& ah)
{
    if (n < N0) {
        int a = n / 361, c = n - a * 361; gy = c / 19; gx = c - gy * 19;
        stride = 32.0f;
        aw = (a == 0) ? 116.0f : (a == 1) ? 156.0f : 373.0f;
        ah = (a == 0) ?  90.0f : (a == 1) ? 198.0f : 326.0f;
        return l0 + (size_t)(((b * 3 + a) * 19 + gy) * 19 + gx) * 26;
    } else if (n < N0 + N1) {
        int r = n - N0;
        int a = r / 1444, c = r - a * 1444; gy = c / 38; gx = c - gy * 38;
        stride = 16.0f;
        aw = (a == 0) ? 30.0f : (a == 1) ? 62.0f : 59.0f;
        ah = (a == 0) ? 61.0f : (a == 1) ? 45.0f : 119.0f;
        return l1 + (size_t)(((b * 3 + a) * 38 + gy) * 38 + gx) * 26;
    } else {
        int r = n - N0 - N1;
        int a = r / 5776, c = r - a * 5776; gy = c / 76; gx = c - gy * 76;
        stride = 8.0f;
        aw = (a == 0) ? 10.0f : (a == 1) ? 16.0f : 33.0f;
        ah = (a == 0) ? 13.0f : (a == 1) ? 30.0f : 23.0f;
        return l2 + (size_t)(((b * 3 + a) * 76 + gy) * 76 + gx) * 26;
    }
}

// ---------------- Kernel 0: init counters ----------------
__global__ void k_init() {
    if (threadIdx.x < NB) g_ncand[threadIdx.x] = 0;
}

// ---------------- Kernel 1: score + compact valid candidates ----------------
// Linear smem staging: STS.128 with zero index math; consumer reads at t*26.
template<int NL, int OFF>
__global__ __launch_bounds__(256) void k_score_lvl(const float* __restrict__ in)
{
    __shared__ float sm[256 * 26];
    int base  = blockIdx.x * 256;
    int total = NB * NL;
    int nrec  = total - base; if (nrec > 256) nrec = 256;
    int nfl   = nrec * 26;
    const float* __restrict__ src = in + (size_t)base * 26;

    int nf4 = nfl >> 2;                       // base*26*4B is 16B-aligned
    const float4* __restrict__ s4 = reinterpret_cast<const float4*>(src);
    float4* __restrict__ d4 = reinterpret_cast<float4*>(sm);
    for (int q = threadIdx.x; q < nf4; q += 256) d4[q] = s4[q];
    for (int f = (nf4 << 2) + threadIdx.x; f < nfl; f += 256) sm[f] = src[f];
    __syncthreads();

    int t = threadIdx.x;
    bool valid = false;
    float score = 0.0f;
    int bimg = 0, nloc = 0;
    if (t < nrec) {
        const float* p = sm + t * 26;
        // cheap raw-logit rejects first: obj>=0.6 <=> p4>=ln(1.5); loc>=0.5 <=> p5>=0
        float p4 = p[4], p5 = p[5];
        if (p4 >= 0.4054651081081644f && p5 >= 0.0f) {
            float obj = 1.0f / (1.0f + expf(-p4));
            float loc = 1.0f / (1.0f + expf(-p5));
            float m = p[6];
#pragma unroll
            for (int i = 1; i < 20; i++) m = fmaxf(m, p[6 + i]);
            float s = 0.0f;
#pragma unroll
            for (int i = 0; i < 20; i++) s += expf(p[6 + i] - m);
            float conf = 1.0f / s;
            valid = (obj >= 0.6f) && (obj * conf >= 0.05f) && (loc >= 0.5f);
            score = sqrtf(obj * conf) * sqrtf(loc);
        }
        int r = base + t;
        bimg = r / NL;
        nloc = r - bimg * NL;
    }

    // warp-aggregated append (a warp spans at most 2 images)
    unsigned lane = threadIdx.x & 31u;
    int b0 = __shfl_sync(0xffffffffu, bimg, 0);
    bool same = (bimg == b0);
    unsigned m_same = __ballot_sync(0xffffffffu, valid && same);
    unsigned m_diff = __ballot_sync(0xffffffffu, valid && !same);
    int pos = -1, bw = 0;
    if (m_same) {
        int leader = __ffs(m_same) - 1;
        int bs = 0;
        if ((int)lane == leader) bs = atomicAdd(&g_ncand[b0], __popc(m_same));
        bs = __shfl_sync(0xffffffffu, bs, leader);
        if (valid && same) { pos = bs + __popc(m_same & ((1u << lane) - 1u)); bw = b0; }
    }
    if (m_diff) {
        int leader = __ffs(m_diff) - 1;
        int b1 = __shfl_sync(0xffffffffu, bimg, leader);
        int bs = 0;
        if ((int)lane == leader) bs = atomicAdd(&g_ncand[b1], __popc(m_diff));
        bs = __shfl_sync(0xffffffffu, bs, leader);
        if (valid && !same) { pos = bs + __popc(m_diff & ((1u << lane) - 1u)); bw = b1; }
    }
    if (pos >= 0) {
        g_vsc [(size_t)bw * NTOT + pos] = score;
        g_vidx[(size_t)bw * NTOT + pos] = OFF + nloc;
    }
}

// ---------------- Kernel 2: exact top-256 (radix, warp scan) + fused decode ----------------
__global__ __launch_bounds__(512) void k_select(
    const float* __restrict__ l0, const float* __restrict__ l1, const float* __restrict__ l2)
{
    int b = blockIdx.x, tid = threadIdx.x;
    const int nth = 512;
    int n = g_ncand[b];
    const float* __restrict__ vs = g_vsc  + (size_t)b * NTOT;
    const int*   __restrict__ vi = g_vidx + (size_t)b * NTOT;

    __shared__ unsigned hist[256];
    __shared__ int sh_chosen, sh_need, sh_abv, cntG, cntE;
    __shared__ int   s_idx[MCAND];
    __shared__ float s_sc [MCAND];

    for (int i = tid; i < MCAND; i += nth) { s_idx[i] = -1; s_sc[i] = NEGV; }
    if (tid < 8) g_kept[b * 8 + tid] = 0u;
    if (tid == 0) { sh_need = MCAND; cntG = 0; cntE = 0; }
    __syncthreads();

    if (n <= MCAND) {
        for (int i = tid; i < n; i += nth) { s_idx[i] = vi[i]; s_sc[i] = vs[i]; }
    } else {
        unsigned prefix = 0;
        for (int p = 0; p < 4; p++) {
            if (tid < 256) hist[tid] = 0;
            __syncthreads();
            int shift = 24 - 8 * p;
            for (int i = tid; i < n; i += nth) {
                unsigned k = __float_as_uint(vs[i]);   // all compacted scores > 0
                if (p == 0 || (k >> (shift + 8)) == prefix)
                    atomicAdd(&hist[(k >> shift) & 255u], 1u);
            }
            __syncthreads();
            int need = sh_need;
            if (tid < 32) {                            // single-warp suffix scan
                unsigned loc[8]; unsigned tot = 0;
#pragma unroll
                for (int j = 7; j >= 0; j--) { tot += hist[tid * 8 + j]; loc[j] = tot; }
                unsigned s = tot;
#pragma unroll
                for (int off = 1; off < 32; off <<= 1) {   // inclusive suffix over lanes
                    unsigned o = __shfl_down_sync(0xffffffffu, s, off);
                    if (tid + off < 32) s += o;
                }
                unsigned above = s - tot;              // sum over lanes > tid
#pragma unroll
                for (int j = 0; j < 8; j++) {
                    unsigned sj  = above + loc[j];
                    unsigned sj1 = (j == 7) ? above : above + loc[j + 1];
                    if ((int)sj >= need && (int)sj1 < need) {
                        sh_chosen = tid * 8 + j; sh_abv = (int)sj1;
                    }
                }
            }
            __syncthreads();
            if (tid == 0) sh_need = need - sh_abv;
            __syncthreads();
            prefix = (prefix << 8) | (unsigned)sh_chosen;
        }
        int need = sh_need;
        unsigned K = prefix;               // exact 256th key
        int nG = MCAND - need;
        for (int i = tid; i < n; i += nth) {
            float v = vs[i];
            unsigned k = __float_as_uint(v);
            int pos = -1;
            if (k > K)       pos = atomicAdd(&cntG, 1);
            else if (k == K) { int e = atomicAdd(&cntE, 1); if (e < need) pos = nG + e; }
            if (pos >= 0) { s_idx[pos] = vi[i]; s_sc[pos] = v; }
        }
    }
    __syncthreads();

    // export scores + fused decode (threads 0..255)
    for (int c = tid; c < MCAND; c += nth) g_cscore[b * MCAND + c] = s_sc[c];
    if (tid < MCAND) {
        int slot = b * MCAND + tid;
        int idx = s_idx[tid];
        float4 bx = make_float4(0.f, 0.f, 0.f, 0.f);
        int cc = -1;
        if (idx >= 0) {
            int gx, gy; float stride, aw, ah;
            const float* p = locate(b, idx, l0, l1, l2, gx, gy, stride, aw, ah);
            float cx = (1.0f / (1.0f + expf(-p[0])) + (float)gx) * stride;
            float cy = (1.0f / (1.0f + expf(-p[1])) + (float)gy) * stride;
            float w  = expf(p[2]) * aw;
            float h  = expf(p[3]) * ah;
            bx.x = fminf(fmaxf(cx - w * 0.5f, 0.0f), 608.0f);
            bx.y = fminf(fmaxf(cy - h * 0.5f, 0.0f), 608.0f);
            bx.z = fminf(fmaxf(cx + w * 0.5f, 0.0f), 608.0f);
            bx.w = fminf(fmaxf(cy + h * 0.5f, 0.0f), 608.0f);
            float best = p[6]; cc = 0;
#pragma unroll
            for (int i = 1; i < 20; i++) {
                float v = p[6 + i];
                if (v > best) { best = v; cc = i; }   // first max, like jnp.argmax
            }
        }
        g_cbox[slot]  = bx;
        g_carea[slot] = (bx.z - bx.x + 1.0f) * (bx.w - bx.y + 1.0f);
        g_ccls[slot]  = cc;
    }
}

// ---------------- Kernel 3: per-(image,class) Gaussian soft-NMS ----------------
// Soft-NMS only decays same-class scores and 256 steps drain every candidate,
// so the kept set decomposes exactly per class. One warp per (image, class).
__global__ __launch_bounds__(32) void k_nms()
{
    int b = blockIdx.x, cl = blockIdx.y, lane = threadIdx.x;
    __shared__ float4 sb[MCAND];
    __shared__ float  sa[MCAND];

    unsigned key[8]; float sc[8]; float4 bx[8]; float a2[8]; bool act[8];
    unsigned any = 0;
#pragma unroll
    for (int j = 0; j < 8; j++) {
        int slot = j * 32 + lane;
        int g = b * MCAND + slot;
        int cc  = g_ccls[g];
        float s = g_cscore[g];
        act[j] = (cc == cl);
        key[j] = act[j] ? __float_as_uint(s) : 0u;
        sc[j]  = s;
        float4 B = g_cbox[g];
        bx[j] = B;
        a2[j] = g_carea[g];
        sb[slot] = B;
        sa[slot] = a2[j];
        any |= key[j];
    }
    __syncwarp();
    if (redux_umax(any) == 0u) return;      // class absent in this image

    unsigned keptloc = 0;
    for (int it = 0; it < MCAND; it++) {
        unsigned lm = 0, li = 0;
#pragma unroll
        for (int j = 0; j < 8; j++)
            if (key[j] > lm) { lm = key[j]; li = (unsigned)(j * 32 + lane); }
        unsigned wm = redux_umax(lm);
        if (__uint_as_float(wm) < NMS_T) break;   // includes wm==0
        unsigned cand = (lm == wm) ? li : 0xFFFFFFFFu;
        unsigned wi = redux_umin(cand);           // first-index tie-break (exact)

        float4 wb = sb[wi];
        float  a1 = sa[wi];
#pragma unroll
        for (int j = 0; j < 8; j++) {
            if (act[j]) {
                float ix1 = fmaxf(wb.x, bx[j].x), iy1 = fmaxf(wb.y, bx[j].y);
                float ix2 = fminf(wb.z, bx[j].z), iy2 = fminf(wb.w, bx[j].w);
                float inter = fmaxf(ix2 - ix1 + 1.0f, 0.0f) * fmaxf(iy2 - iy1 + 1.0f, 0.0f);
                float iou = inter / (a1 + a2[j] - inter + 1e-16f);
                sc[j] *= expf(-(iou * iou) * 2.0f);   // exp(-iou^2 / 0.5)
                key[j] = __float_as_uint(sc[j]);
            }
            if ((unsigned)(j * 32 + lane) == wi) {
                act[j] = false;
                key[j] = 0u;
                keptloc |= 1u << j;
            }
        }
    }
#pragma unroll
    for (int j = 0; j < 8; j++)
        if (keptloc & (1u << j)) atomicOr(&g_kept[b * 8 + j], 1u << lane);
}

// ---------------- Kernel 4: top-8 among kept by ORIGINAL score ----------------
__global__ __launch_bounds__(32) void k_final(float* __restrict__ out)
{
    int b = blockIdx.x, lane = threadIdx.x;
    unsigned key[8]; float so[8];
#pragma unroll
    for (int j = 0; j < 8; j++) {
        int g = b * MCAND + j * 32 + lane;
        bool k = (g_kept[b * 8 + j] >> lane) & 1u;
        float s = g_cscore[g];
        so[j]  = s;
        key[j] = k ? __float_as_uint(s) : 0u;   // kept scores are > 0
    }
    float* ob = out + (size_t)b * 48;
    for (int k = 0; k < 8; k++) {
        unsigned lm = 0, li = 0;
#pragma unroll
        for (int j = 0; j < 8; j++)
            if (key[j] > lm) { lm = key[j]; li = (unsigned)(j * 32 + lane); }
        unsigned wm = redux_umax(lm);
        if (wm == 0u) {
            if (lane == 0) {
#pragma unroll
                for (int i = 0; i < 6; i++) ob[k * 6 + i] = 0.0f;
            }
            continue;
        }
        unsigned cand = (lm == wm) ? li : 0xFFFFFFFFu;
        unsigned wi = redux_umin(cand);
#pragma unroll
        for (int j = 0; j < 8; j++) {
            if ((unsigned)(j * 32 + lane) == wi) {
                int g = b * MCAND + j * 32 + lane;
                float4 B = g_cbox[g];
                ob[k * 6 + 0] = B.x;
                ob[k * 6 + 1] = B.y;
                ob[k * 6 + 2] = B.z;
                ob[k * 6 + 3] = B.w;
                ob[k * 6 + 4] = so[j];
                ob[k * 6 + 5] = (float)g_ccls[g];
                key[j] = 0u;
            }
        }
    }
}

extern "C" void kernel_launch(void* const* d_in, const int* in_sizes, int n_in,
                              void* d_out, int out_size)
{
    const float* l0 = (const float*)d_in[0];
    const float* l1 = (const float*)d_in[1];
    const float* l2 = (const float*)d_in[2];
    float* out = (float*)d_out;

    k_init<<<1, 64>>>();
    k_score_lvl<N0, 0>      <<<(NB * N0 + 255) / 256, 256>>>(l0);
    k_score_lvl<N1, N0>     <<<(NB * N1 + 255) / 256, 256>>>(l1);
    k_score_lvl<N2, N0 + N1><<<(NB * N2 + 255) / 256, 256>>>(l2);
    k_select<<<NB, 512>>>(l0, l1, l2);
    k_nms<<<dim3(NB, 20), 32>>>();
    k_final<<<NB, 32>>>(out);
}

// round 5
// speedup vs baseline: 5.3986x; 1.1741x over previous
#include <cuda_runtime.h>
#include <math.h>

#define NB    64
#define N0    1083     // 3*19*19
#define N1    4332     // 3*38*38
#define N2    17328    // 3*76*76
#define NTOT  22743
#define MCAND 256
#define NEGV  (-1e9f)
#define NMS_T 0.1f

#define NBLK0 ((NB * N0 + 255) / 256)   // 271
#define NBLK1 ((NB * N1) / 256)         // 1083 (exact)
#define NBLK2 ((NB * N2) / 256)         // 4332 (exact)

// scratch (static __device__ — zero-initialized at load; g_ncand reset each call by k_nms_final)
__device__ int      g_ncand[NB];
__device__ float    g_vsc  [NB * NTOT];   // compacted valid scores per image
__device__ int      g_vidx [NB * NTOT];   // compacted flat indices per image
__device__ float    g_cscore[NB * MCAND];
__device__ float4   g_cbox  [NB * MCAND];
__device__ float    g_carea [NB * MCAND];
__device__ int      g_ccls  [NB * MCAND];

__device__ __forceinline__ unsigned redux_umax(unsigned v) {
    unsigned r; asm("redux.sync.max.u32 %0, %1, 0xffffffff;" : "=r"(r) : "r"(v)); return r;
}
__device__ __forceinline__ unsigned redux_umin(unsigned v) {
    unsigned r; asm("redux.sync.min.u32 %0, %1, 0xffffffff;" : "=r"(r) : "r"(v)); return r;
}

// map flat per-image index n -> pred pointer + grid cell + anchor (pixels)
__device__ __forceinline__ const float* locate(
    int b, int n,
    const float* __restrict__ l0, const float* __restrict__ l1, const float* __restrict__ l2,
    int& gx, int& gy, float& stride, float& aw, float& ah)
{
    if (n < N0) {
        int a = n / 361, c = n - a * 361; gy = c / 19; gx = c - gy * 19;
        stride = 32.0f;
        aw = (a == 0) ? 116.0f : (a == 1) ? 156.0f : 373.0f;
        ah = (a == 0) ?  90.0f : (a == 1) ? 198.0f : 326.0f;
        return l0 + (size_t)(((b * 3 + a) * 19 + gy) * 19 + gx) * 26;
    } else if (n < N0 + N1) {
        int r = n - N0;
        int a = r / 1444, c = r - a * 1444; gy = c / 38; gx = c - gy * 38;
        stride = 16.0f;
        aw = (a == 0) ? 30.0f : (a == 1) ? 62.0f : 59.0f;
        ah = (a == 0) ? 61.0f : (a == 1) ? 45.0f : 119.0f;
        return l1 + (size_t)(((b * 3 + a) * 38 + gy) * 38 + gx) * 26;
    } else {
        int r = n - N0 - N1;
        int a = r / 5776, c = r - a * 5776; gy = c / 76; gx = c - gy * 76;
        stride = 8.0f;
        aw = (a == 0) ? 10.0f : (a == 1) ? 16.0f : 33.0f;
        ah = (a == 0) ? 13.0f : (a == 1) ? 30.0f : 23.0f;
        return l2 + (size_t)(((b * 3 + a) * 76 + gy) * 76 + gx) * 26;
    }
}

// ---------------- Kernel 1: fused 3-level score + compact (two-phase) ----------------
__global__ __launch_bounds__(256) void k_score_all(
    const float* __restrict__ l0, const float* __restrict__ l1, const float* __restrict__ l2)
{
    __shared__ float sm[256 * 26];
    __shared__ unsigned short s_list[256];
    __shared__ int s_cnt;

    int blk = blockIdx.x;
    const float* in; int NL, OFF, base;
    if (blk < NBLK0)              { in = l0; NL = N0; OFF = 0;       base = blk * 256; }
    else if (blk < NBLK0 + NBLK1) { in = l1; NL = N1; OFF = N0;      base = (blk - NBLK0) * 256; }
    else                          { in = l2; NL = N2; OFF = N0 + N1; base = (blk - NBLK0 - NBLK1) * 256; }

    int total = NB * NL;
    int nrec  = total - base; if (nrec > 256) nrec = 256;
    int nfl   = nrec * 26;
    const float* __restrict__ src = in + (size_t)base * 26;

    if (threadIdx.x == 0) s_cnt = 0;

    // linear smem staging, pure LDG.128/STS.128, zero index math
    int nf4 = nfl >> 2;                       // base*26*4B is 16B-aligned
    const float4* __restrict__ s4 = reinterpret_cast<const float4*>(src);
    float4* __restrict__ d4 = reinterpret_cast<float4*>(sm);
    for (int q = threadIdx.x; q < nf4; q += 256) d4[q] = s4[q];
    for (int f = (nf4 << 2) + threadIdx.x; f < nfl; f += 256) sm[f] = src[f];
    __syncthreads();

    // ---- phase A: cheap conservative predicate + block compaction ----
    int t = threadIdx.x;
    unsigned lane = t & 31u;
    bool pass = false;
    if (t < nrec) {
        float p4 = sm[t * 26 + 4], p5 = sm[t * 26 + 5];
        // obj>=0.6 <=> p4>=ln(1.5)=0.405465...; loc>=0.5 <=> p5>=0. Conservative slack;
        // the exact test re-runs in phase B.
        pass = (p4 >= 0.405f) && (p5 >= -1e-6f);
    }
    unsigned mball = __ballot_sync(0xffffffffu, pass);
    int bs = 0;
    if (mball) {
        if (lane == 0) bs = atomicAdd(&s_cnt, __popc(mball));
        bs = __shfl_sync(0xffffffffu, bs, 0);
        if (pass) s_list[bs + __popc(mball & ((1u << lane) - 1u))] = (unsigned short)t;
    }
    __syncthreads();
    int cnt = s_cnt;

    // uniform per-block image split (block spans at most 2 images)
    int b_first = base / NL;
    int rem     = base - b_first * NL;

    // ---- phase B: dense expensive scoring on survivors only ----
    bool valid = false;
    float score = 0.0f;
    int bimg = 0, nloc = 0;
    if (t < cnt) {
        int rec = s_list[t];
        const float* p = sm + rec * 26;
        float obj = 1.0f / (1.0f + expf(-p[4]));
        float loc = 1.0f / (1.0f + expf(-p[5]));
        float m = p[6];
#pragma unroll
        for (int i = 1; i < 20; i++) m = fmaxf(m, p[6 + i]);
        float s = 0.0f;
#pragma unroll
        for (int i = 0; i < 20; i++) s += expf(p[6 + i] - m);
        float conf = 1.0f / s;
        valid = (obj >= 0.6f) && (obj * conf >= 0.05f) && (loc >= 0.5f);
        score = sqrtf(obj * conf) * sqrtf(loc);
        int r_off = rec + rem;
        int over  = (r_off >= NL);
        bimg = b_first + over;
        nloc = r_off - (over ? NL : 0);
    }

    // warp-aggregated append (a warp's survivors span at most 2 images)
    int b0 = __shfl_sync(0xffffffffu, bimg, 0);
    bool same = (bimg == b0);
    unsigned m_same = __ballot_sync(0xffffffffu, valid && same);
    unsigned m_diff = __ballot_sync(0xffffffffu, valid && !same);
    int pos = -1, bw = 0;
    if (m_same) {
        int leader = __ffs(m_same) - 1;
        int base2 = 0;
        if ((int)lane == leader) base2 = atomicAdd(&g_ncand[b0], __popc(m_same));
        base2 = __shfl_sync(0xffffffffu, base2, leader);
        if (valid && same) { pos = base2 + __popc(m_same & ((1u << lane) - 1u)); bw = b0; }
    }
    if (m_diff) {
        int leader = __ffs(m_diff) - 1;
        int b1 = __shfl_sync(0xffffffffu, bimg, leader);
        int base2 = 0;
        if ((int)lane == leader) base2 = atomicAdd(&g_ncand[b1], __popc(m_diff));
        base2 = __shfl_sync(0xffffffffu, base2, leader);
        if (valid && !same) { pos = base2 + __popc(m_diff & ((1u << lane) - 1u)); bw = b1; }
    }
    if (pos >= 0) {
        g_vsc [(size_t)bw * NTOT + pos] = score;
        g_vidx[(size_t)bw * NTOT + pos] = OFF + nloc;
    }
}

// ---------------- Kernel 2: exact top-256 (radix, warp scan) + fused decode ----------------
__global__ __launch_bounds__(512) void k_select(
    const float* __restrict__ l0, const float* __restrict__ l1, const float* __restrict__ l2)
{
    int b = blockIdx.x, tid = threadIdx.x;
    const int nth = 512;
    int n = g_ncand[b];
    const float* __restrict__ vs = g_vsc  + (size_t)b * NTOT;
    const int*   __restrict__ vi = g_vidx + (size_t)b * NTOT;

    __shared__ unsigned hist[256];
    __shared__ int sh_chosen, sh_need, sh_abv, cntG, cntE;
    __shared__ int   s_idx[MCAND];
    __shared__ float s_sc [MCAND];

    for (int i = tid; i < MCAND; i += nth) { s_idx[i] = -1; s_sc[i] = NEGV; }
    if (tid == 0) { sh_need = MCAND; cntG = 0; cntE = 0; }
    __syncthreads();

    if (n <= MCAND) {
        for (int i = tid; i < n; i += nth) { s_idx[i] = vi[i]; s_sc[i] = vs[i]; }
    } else {
        unsigned prefix = 0;
        for (int p = 0; p < 4; p++) {
            if (tid < 256) hist[tid] = 0;
            __syncthreads();
            int shift = 24 - 8 * p;
            for (int i = tid; i < n; i += nth) {
                unsigned k = __float_as_uint(vs[i]);   // all compacted scores > 0
                if (p == 0 || (k >> (shift + 8)) == prefix)
                    atomicAdd(&hist[(k >> shift) & 255u], 1u);
            }
            __syncthreads();
            int need = sh_need;
            if (tid < 32) {                            // single-warp suffix scan
                unsigned loc[8]; unsigned tot = 0;
#pragma unroll
                for (int j = 7; j >= 0; j--) { tot += hist[tid * 8 + j]; loc[j] = tot; }
                unsigned s = tot;
#pragma unroll
                for (int off = 1; off < 32; off <<= 1) {
                    unsigned o = __shfl_down_sync(0xffffffffu, s, off);
                    if (tid + off < 32) s += o;
                }
                unsigned above = s - tot;              // sum over lanes > tid
#pragma unroll
                for (int j = 0; j < 8; j++) {
                    unsigned sj  = above + loc[j];
                    unsigned sj1 = (j == 7) ? above : above + loc[j + 1];
                    if ((int)sj >= need && (int)sj1 < need) {
                        sh_chosen = tid * 8 + j; sh_abv = (int)sj1;
                    }
                }
            }
            __syncthreads();
            if (tid == 0) sh_need = need - sh_abv;
            __syncthreads();
            prefix = (prefix << 8) | (unsigned)sh_chosen;
        }
        int need = sh_need;
        unsigned K = prefix;               // exact 256th key
        int nG = MCAND - need;
        for (int i = tid; i < n; i += nth) {
            float v = vs[i];
            unsigned k = __float_as_uint(v);
            int pos = -1;
            if (k > K)       pos = atomicAdd(&cntG, 1);
            else if (k == K) { int e = atomicAdd(&cntE, 1); if (e < need) pos = nG + e; }
            if (pos >= 0) { s_idx[pos] = vi[i]; s_sc[pos] = v; }
        }
    }
    __syncthreads();

    for (int c = tid; c < MCAND; c += nth) g_cscore[b * MCAND + c] = s_sc[c];
    if (tid < MCAND) {
        int slot = b * MCAND + tid;
        int idx = s_idx[tid];
        float4 bx = make_float4(0.f, 0.f, 0.f, 0.f);
        int cc = -1;
        if (idx >= 0) {
            int gx, gy; float stride, aw, ah;
            const float* p = locate(b, idx, l0, l1, l2, gx, gy, stride, aw, ah);
            float cx = (1.0f / (1.0f + expf(-p[0])) + (float)gx) * stride;
            float cy = (1.0f / (1.0f + expf(-p[1])) + (float)gy) * stride;
            float w  = expf(p[2]) * aw;
            float h  = expf(p[3]) * ah;
            bx.x = fminf(fmaxf(cx - w * 0.5f, 0.0f), 608.0f);
            bx.y = fminf(fmaxf(cy - h * 0.5f, 0.0f), 608.0f);
            bx.z = fminf(fmaxf(cx + w * 0.5f, 0.0f), 608.0f);
            bx.w = fminf(fmaxf(cy + h * 0.5f, 0.0f), 608.0f);
            float best = p[6]; cc = 0;
#pragma unroll
            for (int i = 1; i < 20; i++) {
                float v = p[6 + i];
                if (v > best) { best = v; cc = i; }   // first max, like jnp.argmax
            }
        }
        g_cbox[slot]  = bx;
        g_carea[slot] = (bx.z - bx.x + 1.0f) * (bx.w - bx.y + 1.0f);
        g_ccls[slot]  = cc;
    }
}

// ---------------- Kernel 3: fused per-image NMS (20 class warps) + top-8 output ----------------
// Soft-NMS only decays same-class scores and 256 steps drain every candidate,
// so the kept set decomposes exactly per class. One 640-thread block per image.
__global__ __launch_bounds__(640) void k_nms_final(float* __restrict__ out)
{
    int b = blockIdx.x;
    int tid = threadIdx.x;
    int wid = tid >> 5, lane = tid & 31;

    __shared__ float4   sb [MCAND];
    __shared__ float    sa [MCAND];
    __shared__ float    ssc[MCAND];
    __shared__ int      scl[MCAND];
    __shared__ unsigned skept[8];

    for (int i = tid; i < MCAND; i += 640) {
        int g = b * MCAND + i;
        sb[i]  = g_cbox[g];
        sa[i]  = g_carea[g];
        ssc[i] = g_cscore[g];
        scl[i] = g_ccls[g];
    }
    if (tid < 8) skept[tid] = 0u;
    if (tid == 0) g_ncand[b] = 0;        // reset counter for next call (zero-init at load)
    __syncthreads();

    // --- per-class soft-NMS: warp `wid` handles class `wid` (20 warps) ---
    {
        int cl = wid;
        unsigned key[8]; float sc[8]; float4 bx[8]; float a2[8]; bool act[8];
        unsigned any = 0;
#pragma unroll
        for (int j = 0; j < 8; j++) {
            int slot = j * 32 + lane;
            float s = ssc[slot];
            act[j] = (scl[slot] == cl);
            key[j] = act[j] ? __float_as_uint(s) : 0u;
            sc[j]  = s;
            bx[j]  = sb[slot];
            a2[j]  = sa[slot];
            any   |= key[j];
        }
        if (redux_umax(any) != 0u) {
            unsigned keptloc = 0;
            for (int it = 0; it < MCAND; it++) {
                unsigned lm = 0, li = 0;
#pragma unroll
                for (int j = 0; j < 8; j++)
                    if (key[j] > lm) { lm = key[j]; li = (unsigned)(j * 32 + lane); }
                unsigned wm = redux_umax(lm);
                if (__uint_as_float(wm) < NMS_T) break;   // includes wm==0
                unsigned cand = (lm == wm) ? li : 0xFFFFFFFFu;
                unsigned wi = redux_umin(cand);           // first-index tie-break (exact)

                float4 wb = sb[wi];
                float  a1 = sa[wi];
#pragma unroll
                for (int j = 0; j < 8; j++) {
                    if (act[j]) {
                        float ix1 = fmaxf(wb.x, bx[j].x), iy1 = fmaxf(wb.y, bx[j].y);
                        float ix2 = fminf(wb.z, bx[j].z), iy2 = fminf(wb.w, bx[j].w);
                        float inter = fmaxf(ix2 - ix1 + 1.0f, 0.0f) * fmaxf(iy2 - iy1 + 1.0f, 0.0f);
                        float iou = inter / (a1 + a2[j] - inter + 1e-16f);
                        sc[j] *= expf(-(iou * iou) * 2.0f);   // exp(-iou^2 / 0.5)
                        key[j] = __float_as_uint(sc[j]);
                    }
                    if ((unsigned)(j * 32 + lane) == wi) {
                        act[j] = false;
                        key[j] = 0u;
                        keptloc |= 1u << j;
                    }
                }
            }
#pragma unroll
            for (int j = 0; j < 8; j++)
                if (keptloc & (1u << j)) atomicOr(&skept[j], 1u << lane);
        }
    }
    __syncthreads();

    // --- warp 0: top-8 among kept by ORIGINAL score ---
    if (wid == 0) {
        unsigned key[8]; float so[8];
#pragma unroll
        for (int j = 0; j < 8; j++) {
            int slot = j * 32 + lane;
            bool k = (skept[j] >> lane) & 1u;
            float s = ssc[slot];
            so[j]  = s;
            key[j] = k ? __float_as_uint(s) : 0u;   // kept scores are > 0
        }
        float* ob = out + (size_t)b * 48;
        for (int k = 0; k < 8; k++) {
            unsigned lm = 0, li = 0;
#pragma unroll
            for (int j = 0; j < 8; j++)
                if (key[j] > lm) { lm = key[j]; li = (unsigned)(j * 32 + lane); }
            unsigned wm = redux_umax(lm);
            if (wm == 0u) {
                if (lane == 0) {
#pragma unroll
                    for (int i = 0; i < 6; i++) ob[k * 6 + i] = 0.0f;
                }
                continue;
            }
            unsigned cand = (lm == wm) ? li : 0xFFFFFFFFu;
            unsigned wi = redux_umin(cand);
#pragma unroll
            for (int j = 0; j < 8; j++) {
                if ((unsigned)(j * 32 + lane) == wi) {
                    int slot = j * 32 + lane;
                    float4 B = sb[slot];
                    ob[k * 6 + 0] = B.x;
                    ob[k * 6 + 1] = B.y;
                    ob[k * 6 + 2] = B.z;
                    ob[k * 6 + 3] = B.w;
                    ob[k * 6 + 4] = so[j];
                    ob[k * 6 + 5] = (float)scl[slot];
                    key[j] = 0u;
                }
            }
        }
    }
}

extern "C" void kernel_launch(void* const* d_in, const int* in_sizes, int n_in,
                              void* d_out, int out_size)
{
    const float* l0 = (const float*)d_in[0];
    const float* l1 = (const float*)d_in[1];
    const float* l2 = (const float*)d_in[2];
    float* out = (float*)d_out;

    k_score_all<<<NBLK0 + NBLK1 + NBLK2, 256>>>(l0, l1, l2);
    k_select<<<NB, 512>>>(l0, l1, l2);
    k_nms_final<<<NB, 640>>>(out);
}